// round 10
// baseline (speedup 1.0000x reference)
#include <cuda_runtime.h>
#include <cstdint>

// Problem constants
#define B_WIN 4096
#define N_TOK 49
#define C_DIM 128
#define H_HEADS 4
#define HD 32
#define M_ROWS (B_WIN * N_TOK)   // 200704 = 1568 * 128 exactly

// Scratch: __device__ globals (no allocations allowed)
__device__ float g_q[B_WIN * H_HEADS * N_TOK * HD];   // [b][h][n][d]
__device__ float g_k[B_WIN * H_HEADS * N_TOK * HD];
__device__ float g_v[B_WIN * H_HEADS * N_TOK * HD];
__device__ float g_ao[(size_t)M_ROWS * C_DIM];        // attention output [b*n][c]
__device__ float g_comb[64 * H_HEADS * N_TOK * N_TOK]; // bias+mask [w][h][n][m]

// ---------------------------------------------------------------------------
// comb precompute
// ---------------------------------------------------------------------------
__global__ void comb_kernel(const float* __restrict__ mask,
                            const float* __restrict__ bias_table,
                            const int* __restrict__ rel32, int idx_stride) {
    const int w = blockIdx.x;
    const int h = blockIdx.y;
    float* dst = g_comb + ((size_t)w * H_HEADS + h) * 2401;
    const float* msk = mask + (size_t)w * 2401;
    for (int e = threadIdx.x; e < 2401; e += blockDim.x) {
        int idx = rel32[e * idx_stride];
        dst[e] = bias_table[idx * H_HEADS + h] + msk[e];
    }
}

// ---------------------------------------------------------------------------
// Packed fp32x2 + cp.async helpers
// ---------------------------------------------------------------------------
__device__ __forceinline__ unsigned long long pack_dup(float a) {
    unsigned long long r;
    uint32_t ai = __float_as_uint(a);
    asm("mov.b64 %0, {%1, %1};" : "=l"(r) : "r"(ai));
    return r;
}
__device__ __forceinline__ void ffma2(unsigned long long& c, unsigned long long a,
                                      unsigned long long b) {
    asm("fma.rn.f32x2 %0, %1, %2, %0;" : "+l"(c) : "l"(a), "l"(b));
}
__device__ __forceinline__ float lo32(unsigned long long v) {
    return __uint_as_float((uint32_t)v);
}
__device__ __forceinline__ float hi32(unsigned long long v) {
    return __uint_as_float((uint32_t)(v >> 32));
}
__device__ __forceinline__ void cpasync16(uint32_t dst, const void* src) {
    asm volatile("cp.async.cg.shared.global [%0], [%1], 16;" :: "r"(dst), "l"(src));
}
__device__ __forceinline__ void cp_commit() {
    asm volatile("cp.async.commit_group;");
}
__device__ __forceinline__ void cp_wait1() {
    asm volatile("cp.async.wait_group 1;");
}
__device__ __forceinline__ void cp_wait0() {
    asm volatile("cp.async.wait_group 0;");
}

// A stage: [128 m][20 words] (16 k + 4 pad), row = 80 B (16-aligned; two ty
//          addrs per warp differ by 16 banks -> conflict-free broadcast)
// B stage: [16 k][132 words] (128 n + 4 pad), row = 528 B (16-aligned)
#define AP 20
#define A_STAGE (128 * AP)
#define B_STAGE (16 * 132)

// ---------------------------------------------------------------------------
// QKV GEMM, cp.async double-buffered, FFMA2. Bit-identical accumulation
// order to the R8 kernel (k ascending).
// ---------------------------------------------------------------------------
__global__ __launch_bounds__(256) void qkv_gemm(const float* __restrict__ A,
                                                const float* __restrict__ B,
                                                const float* __restrict__ bias) {
    __shared__ float As[2][A_STAGE];
    __shared__ float Bs[2][B_STAGE];

    const int tid = threadIdx.x;
    const int tx = tid & 15;
    const int ty = tid >> 4;
    const int m0 = blockIdx.x * 128;
    const int t3 = blockIdx.y;      // 0=q, 1=k, 2=v

    unsigned long long pacc[8][4];
#pragma unroll
    for (int i = 0; i < 8; i++)
#pragma unroll
        for (int j = 0; j < 4; j++) pacc[i][j] = 0ull;

    const float4* A4 = reinterpret_cast<const float4*>(A);
    const float4* B4 = reinterpret_cast<const float4*>(B);
    const uint32_t asb0 = (uint32_t)__cvta_generic_to_shared(&As[0][0]);
    const uint32_t asb1 = (uint32_t)__cvta_generic_to_shared(&As[1][0]);
    const uint32_t bsb0 = (uint32_t)__cvta_generic_to_shared(&Bs[0][0]);
    const uint32_t bsb1 = (uint32_t)__cvta_generic_to_shared(&Bs[1][0]);

    auto prefetch = [&](int kc, int s) {
        uint32_t ab = s ? asb1 : asb0;
        uint32_t bb = s ? bsb1 : bsb0;
        // A chunk: 128 m x 16 k = 512 float4s, 2 per thread
#pragma unroll
        for (int t = 0; t < 2; t++) {
            int flat = tid + t * 256;
            int m = flat >> 2;
            int k4 = flat & 3;
            cpasync16(ab + (uint32_t)(m * 80 + k4 * 16),
                      A4 + (size_t)(m0 + m) * 32 + kc * 4 + k4);
        }
        // B chunk: 16 k x 128 n = 512 float4s, 2 per thread
#pragma unroll
        for (int t = 0; t < 2; t++) {
            int flat = tid + t * 256;
            int kk = flat >> 5;
            int n4 = flat & 31;
            cpasync16(bb + (uint32_t)(kk * 528 + n4 * 16),
                      B4 + (size_t)(kc * 16 + kk) * 96 + t3 * 32 + n4);
        }
        cp_commit();
    };

    prefetch(0, 0);
    prefetch(1, 1);

#pragma unroll 1
    for (int kc = 0; kc < 8; kc++) {
        if (kc < 7) cp_wait1(); else cp_wait0();
        __syncthreads();

        const float* as = As[kc & 1];
        const float* bs = Bs[kc & 1];
#pragma unroll 2
        for (int kk = 0; kk < 16; kk += 2) {
            float2 af[8];
#pragma unroll
            for (int i = 0; i < 4; i++) {
                af[i] = *reinterpret_cast<const float2*>(&as[(ty * 4 + i) * AP + kk]);
                af[4 + i] = *reinterpret_cast<const float2*>(
                    &as[(64 + ty * 4 + i) * AP + kk]);
            }
#pragma unroll
            for (int j = 0; j < 2; j++) {
                const float* br = &bs[(kk + j) * 132];
                unsigned long long bp0 =
                    *reinterpret_cast<const unsigned long long*>(&br[tx * 4]);
                unsigned long long bp1 =
                    *reinterpret_cast<const unsigned long long*>(&br[tx * 4 + 2]);
                unsigned long long bp2 =
                    *reinterpret_cast<const unsigned long long*>(&br[64 + tx * 4]);
                unsigned long long bp3 =
                    *reinterpret_cast<const unsigned long long*>(&br[64 + tx * 4 + 2]);
#pragma unroll
                for (int i = 0; i < 8; i++) {
                    unsigned long long aa = pack_dup(j ? af[i].y : af[i].x);
                    ffma2(pacc[i][0], aa, bp0);
                    ffma2(pacc[i][1], aa, bp1);
                    ffma2(pacc[i][2], aa, bp2);
                    ffma2(pacc[i][3], aa, bp3);
                }
            }
        }
        __syncthreads();
        if (kc < 6) prefetch(kc + 2, kc & 1);
    }

    // Epilogue: scatter to q/k/v [b][h][n][d]
    float* dst = (t3 == 0) ? g_q : ((t3 == 1) ? g_k : g_v);
    const float scale = (t3 == 0) ? 0.17677669529663687f : 1.0f;  // 32^-0.5

#pragma unroll
    for (int ih = 0; ih < 2; ih++) {
#pragma unroll
        for (int i = 0; i < 4; i++) {
            int r = ih * 64 + ty * 4 + i;
            int gm = m0 + r;
            int b = gm / 49;
            int n = gm - b * 49;
#pragma unroll
            for (int jh = 0; jh < 2; jh++) {
                int c = jh * 64 + tx * 4;
                int h = c >> 5;
                int d = c & 31;
                unsigned long long p0 = pacc[ih * 4 + i][jh * 2 + 0];
                unsigned long long p1 = pacc[ih * 4 + i][jh * 2 + 1];
                float4 o;
                o.x = (lo32(p0) + bias[t3 * 128 + c + 0]) * scale;
                o.y = (hi32(p0) + bias[t3 * 128 + c + 1]) * scale;
                o.z = (lo32(p1) + bias[t3 * 128 + c + 2]) * scale;
                o.w = (hi32(p1) + bias[t3 * 128 + c + 3]) * scale;
                *reinterpret_cast<float4*>(
                    &dst[(((size_t)b * H_HEADS + h) * N_TOK + n) * HD + d]) = o;
            }
        }
    }
}

// ---------------------------------------------------------------------------
// Attention v3 (unchanged from R9, passing).
// ---------------------------------------------------------------------------
__global__ __launch_bounds__(128) void attn_kernel() {
    __shared__ float qs[56 * 33];    // [n][k]
    __shared__ float ks_t[32 * 68];  // [k][m]  (transposed K)
    __shared__ float vs[49 * 36];    // [m][d]
    __shared__ float P[56 * 53];     // normalized probs [n][m]

    const int tid = threadIdx.x;
    const int b = blockIdx.x;
    const int h = blockIdx.y;

    const size_t base4 = (((size_t)b * H_HEADS + h) * N_TOK) * 8;  // float4 units
    const float4* q4 = reinterpret_cast<const float4*>(g_q);
    const float4* k4p = reinterpret_cast<const float4*>(g_k);
    const float4* v4 = reinterpret_cast<const float4*>(g_v);
    for (int f = tid; f < 49 * 8; f += 128) {
        int row = f >> 3;
        int c4 = f & 7;
        float4 vq = q4[base4 + f];
        float4 vk = k4p[base4 + f];
        float4 vv = v4[base4 + f];
        int o = row * 33 + c4 * 4;
        qs[o + 0] = vq.x; qs[o + 1] = vq.y; qs[o + 2] = vq.z; qs[o + 3] = vq.w;
        ks_t[(c4 * 4 + 0) * 68 + row] = vk.x;
        ks_t[(c4 * 4 + 1) * 68 + row] = vk.y;
        ks_t[(c4 * 4 + 2) * 68 + row] = vk.z;
        ks_t[(c4 * 4 + 3) * 68 + row] = vk.w;
        *reinterpret_cast<float4*>(&vs[row * 36 + c4 * 4]) = vv;
    }
    __syncthreads();

    const int rowg = tid >> 4;   // 0..7
    const int colg = tid & 15;   // 0..15

    unsigned long long pacc[7][2];
#pragma unroll
    for (int a = 0; a < 7; a++) { pacc[a][0] = 0ull; pacc[a][1] = 0ull; }

#pragma unroll 4
    for (int k = 0; k < 32; k++) {
        unsigned long long kp0 =
            *reinterpret_cast<const unsigned long long*>(&ks_t[k * 68 + colg * 4]);
        unsigned long long kp1 =
            *reinterpret_cast<const unsigned long long*>(&ks_t[k * 68 + colg * 4 + 2]);
#pragma unroll
        for (int a = 0; a < 7; a++) {
            unsigned long long qq = pack_dup(qs[(rowg * 7 + a) * 33 + k]);
            ffma2(pacc[a][0], qq, kp0);
            ffma2(pacc[a][1], qq, kp1);
        }
    }

    {
        const float* cb = g_comb + ((size_t)((b & 63) * H_HEADS + h)) * 2401;
#pragma unroll
        for (int a = 0; a < 7; a++) {
            int n = rowg * 7 + a;
            float v0 = lo32(pacc[a][0]);
            float v1 = hi32(pacc[a][0]);
            float v2 = lo32(pacc[a][1]);
            float v3 = hi32(pacc[a][1]);
            int m0c = colg * 4;
            if (n < 49) {
                const float* cr = cb + n * 49 + m0c;
                v0 = (m0c + 0 < 49) ? v0 + cr[0] : -1e30f;
                v1 = (m0c + 1 < 49) ? v1 + cr[1] : -1e30f;
                v2 = (m0c + 2 < 49) ? v2 + cr[2] : -1e30f;
                v3 = (m0c + 3 < 49) ? v3 + cr[3] : -1e30f;
            } else {
                v0 = v1 = v2 = v3 = -1e30f;
            }
            float mx = fmaxf(fmaxf(v0, v1), fmaxf(v2, v3));
#pragma unroll
            for (int ofs = 1; ofs < 16; ofs <<= 1)
                mx = fmaxf(mx, __shfl_xor_sync(0xffffffffu, mx, ofs, 16));
            float e0 = __expf(v0 - mx);
            float e1 = __expf(v1 - mx);
            float e2 = __expf(v2 - mx);
            float e3 = __expf(v3 - mx);
            float sm = (e0 + e1) + (e2 + e3);
#pragma unroll
            for (int ofs = 1; ofs < 16; ofs <<= 1)
                sm += __shfl_xor_sync(0xffffffffu, sm, ofs, 16);
            float inv = 1.0f / sm;
            float* pr = &P[n * 53 + m0c];
            if (m0c + 0 < 49) pr[0] = e0 * inv;
            if (m0c + 1 < 49) pr[1] = e1 * inv;
            if (m0c + 2 < 49) pr[2] = e2 * inv;
            if (m0c + 3 < 49) pr[3] = e3 * inv;
        }
    }
    __syncthreads();

    {
        float acc2[7][2];
#pragma unroll
        for (int a = 0; a < 7; a++) { acc2[a][0] = 0.0f; acc2[a][1] = 0.0f; }

#pragma unroll 7
        for (int m = 0; m < 49; m++) {
            float2 vf = *reinterpret_cast<const float2*>(&vs[m * 36 + colg * 2]);
#pragma unroll
            for (int a = 0; a < 7; a++) {
                float pf = P[(rowg * 7 + a) * 53 + m];
                acc2[a][0] = fmaf(pf, vf.x, acc2[a][0]);
                acc2[a][1] = fmaf(pf, vf.y, acc2[a][1]);
            }
        }

#pragma unroll
        for (int a = 0; a < 7; a++) {
            int n = rowg * 7 + a;
            if (n < 49) {
                float2 o = make_float2(acc2[a][0], acc2[a][1]);
                *reinterpret_cast<float2*>(
                    &g_ao[((size_t)b * N_TOK + n) * C_DIM + h * HD + colg * 2]) = o;
            }
        }
    }
}

// ---------------------------------------------------------------------------
// Proj GEMM, cp.async double-buffered, FFMA2.
// ---------------------------------------------------------------------------
__global__ __launch_bounds__(256) void proj_gemm(const float* __restrict__ B,
                                                 const float* __restrict__ bias,
                                                 float* __restrict__ out) {
    __shared__ float As[2][A_STAGE];
    __shared__ float Bs[2][B_STAGE];

    const int tid = threadIdx.x;
    const int tx = tid & 15;
    const int ty = tid >> 4;
    const int m0 = blockIdx.x * 128;

    unsigned long long pacc[8][4];
#pragma unroll
    for (int i = 0; i < 8; i++)
#pragma unroll
        for (int j = 0; j < 4; j++) pacc[i][j] = 0ull;

    const float4* A4 = reinterpret_cast<const float4*>(g_ao);
    const float4* B4 = reinterpret_cast<const float4*>(B);
    const uint32_t asb0 = (uint32_t)__cvta_generic_to_shared(&As[0][0]);
    const uint32_t asb1 = (uint32_t)__cvta_generic_to_shared(&As[1][0]);
    const uint32_t bsb0 = (uint32_t)__cvta_generic_to_shared(&Bs[0][0]);
    const uint32_t bsb1 = (uint32_t)__cvta_generic_to_shared(&Bs[1][0]);

    auto prefetch = [&](int kc, int s) {
        uint32_t ab = s ? asb1 : asb0;
        uint32_t bb = s ? bsb1 : bsb0;
#pragma unroll
        for (int t = 0; t < 2; t++) {
            int flat = tid + t * 256;
            int m = flat >> 2;
            int k4 = flat & 3;
            cpasync16(ab + (uint32_t)(m * 80 + k4 * 16),
                      A4 + (size_t)(m0 + m) * 32 + kc * 4 + k4);
        }
#pragma unroll
        for (int t = 0; t < 2; t++) {
            int flat = tid + t * 256;
            int kk = flat >> 5;
            int n4 = flat & 31;
            cpasync16(bb + (uint32_t)(kk * 528 + n4 * 16),
                      B4 + (size_t)(kc * 16 + kk) * 32 + n4);
        }
        cp_commit();
    };

    prefetch(0, 0);
    prefetch(1, 1);

#pragma unroll 1
    for (int kc = 0; kc < 8; kc++) {
        if (kc < 7) cp_wait1(); else cp_wait0();
        __syncthreads();

        const float* as = As[kc & 1];
        const float* bs = Bs[kc & 1];
#pragma unroll 2
        for (int kk = 0; kk < 16; kk += 2) {
            float2 af[8];
#pragma unroll
            for (int i = 0; i < 4; i++) {
                af[i] = *reinterpret_cast<const float2*>(&as[(ty * 4 + i) * AP + kk]);
                af[4 + i] = *reinterpret_cast<const float2*>(
                    &as[(64 + ty * 4 + i) * AP + kk]);
            }
#pragma unroll
            for (int j = 0; j < 2; j++) {
                const float* br = &bs[(kk + j) * 132];
                unsigned long long bp0 =
                    *reinterpret_cast<const unsigned long long*>(&br[tx * 4]);
                unsigned long long bp1 =
                    *reinterpret_cast<const unsigned long long*>(&br[tx * 4 + 2]);
                unsigned long long bp2 =
                    *reinterpret_cast<const unsigned long long*>(&br[64 + tx * 4]);
                unsigned long long bp3 =
                    *reinterpret_cast<const unsigned long long*>(&br[64 + tx * 4 + 2]);
#pragma unroll
                for (int i = 0; i < 8; i++) {
                    unsigned long long aa = pack_dup(j ? af[i].y : af[i].x);
                    ffma2(pacc[i][0], aa, bp0);
                    ffma2(pacc[i][1], aa, bp1);
                    ffma2(pacc[i][2], aa, bp2);
                    ffma2(pacc[i][3], aa, bp3);
                }
            }
        }
        __syncthreads();
        if (kc < 6) prefetch(kc + 2, kc & 1);
    }

#pragma unroll
    for (int ih = 0; ih < 2; ih++) {
#pragma unroll
        for (int i = 0; i < 4; i++) {
            int r = ih * 64 + ty * 4 + i;
            size_t gm = (size_t)m0 + r;
#pragma unroll
            for (int jh = 0; jh < 2; jh++) {
                int c = jh * 64 + tx * 4;
                unsigned long long p0 = pacc[ih * 4 + i][jh * 2 + 0];
                unsigned long long p1 = pacc[ih * 4 + i][jh * 2 + 1];
                float4 o;
                o.x = lo32(p0) + bias[c + 0];
                o.y = hi32(p0) + bias[c + 1];
                o.z = lo32(p1) + bias[c + 2];
                o.w = hi32(p1) + bias[c + 3];
                *reinterpret_cast<float4*>(&out[gm * C_DIM + c]) = o;
            }
        }
    }
}

// ---------------------------------------------------------------------------
extern "C" void kernel_launch(void* const* d_in, const int* in_sizes, int n_in,
                              void* d_out, int out_size) {
    const float* x          = (const float*)d_in[0];
    const float* mask       = (const float*)d_in[1];
    const float* qkv_w      = (const float*)d_in[2];
    const float* qkv_b      = (const float*)d_in[3];
    const float* proj_w     = (const float*)d_in[4];
    const float* proj_b     = (const float*)d_in[5];
    const float* bias_table = (const float*)d_in[6];
    const int*   rel32      = (const int*)d_in[7];

    int idx_stride = (in_sizes[7] >= 2401 * 2) ? 2 : 1;

    comb_kernel<<<dim3(64, H_HEADS), 256>>>(mask, bias_table, rel32, idx_stride);
    qkv_gemm<<<dim3(M_ROWS / 128, 3), 256>>>(x, qkv_w, qkv_b);
    attn_kernel<<<dim3(B_WIN, H_HEADS), 128>>>();
    proj_gemm<<<dim3(M_ROWS / 128, 1), 256>>>(proj_w, proj_b, (float*)d_out);
}

// round 13
// speedup vs baseline: 1.0244x; 1.0244x over previous
#include <cuda_runtime.h>
#include <cstdint>

// Problem constants
#define B_WIN 4096
#define N_TOK 49
#define C_DIM 128
#define H_HEADS 4
#define HD 32
#define M_ROWS (B_WIN * N_TOK)   // 200704 = 1568 * 128 exactly
#define BP 136                    // Bs row stride (words): double-staggered

typedef unsigned long long ull;

// Scratch: __device__ globals (no allocations allowed)
__device__ float g_q[B_WIN * H_HEADS * N_TOK * HD];   // [b][h][n][d]
__device__ float g_k[B_WIN * H_HEADS * N_TOK * HD];
__device__ float g_v[B_WIN * H_HEADS * N_TOK * HD];
__device__ float g_ao[(size_t)M_ROWS * C_DIM];        // attention output [b*n][c]
__device__ float g_comb[64 * H_HEADS * N_TOK * N_TOK]; // bias+mask [w][h][n][m]

// ---------------------------------------------------------------------------
// comb precompute
// ---------------------------------------------------------------------------
__global__ void comb_kernel(const float* __restrict__ mask,
                            const float* __restrict__ bias_table,
                            const int* __restrict__ rel32, int idx_stride) {
    const int w = blockIdx.x;
    const int h = blockIdx.y;
    float* dst = g_comb + ((size_t)w * H_HEADS + h) * 2401;
    const float* msk = mask + (size_t)w * 2401;
    for (int e = threadIdx.x; e < 2401; e += blockDim.x) {
        int idx = rel32[e * idx_stride];
        dst[e] = bias_table[idx * H_HEADS + h] + msk[e];
    }
}

// ---------------------------------------------------------------------------
// Packed fp32x2 helpers (exact per-lane fp32 FMA).
// ---------------------------------------------------------------------------
__device__ __forceinline__ ull pack_dup(float a) {
    ull r;
    uint32_t ai = __float_as_uint(a);
    asm("mov.b64 %0, {%1, %1};" : "=l"(r) : "r"(ai));
    return r;
}
__device__ __forceinline__ void ffma2(ull& c, ull a, ull b) {
    asm("fma.rn.f32x2 %0, %1, %2, %0;" : "+l"(c) : "l"(a), "l"(b));
}
__device__ __forceinline__ float lo32(ull v) { return __uint_as_float((uint32_t)v); }
__device__ __forceinline__ float hi32(ull v) {
    return __uint_as_float((uint32_t)(v >> 32));
}

// B swizzle: column group g (4 words) stored at g*4 + ((g&8)>>2) + ((g&16)>>2).
// Monotone (no overlaps): groups 0-7 @0-31, 8-15 @34-65, 16-23 @68-99,
// 24-31 @102-133. Consumer: half0 @ tx*4+sx, half1 @ 68+tx*4+sx, sx=(tx&8)>>2.
// Lanes tx / tx+8 hit disjoint bank pairs -> conflict-free LDS.64.

// ---------------------------------------------------------------------------
// QKV GEMM (fp32, FFMA2, conflict-free B)
// ---------------------------------------------------------------------------
__global__ __launch_bounds__(256) void qkv_gemm(const float* __restrict__ A,
                                                const float* __restrict__ B,
                                                const float* __restrict__ bias) {
    __shared__ float As[32 * 132];  // [k][m], padded stride 132
    __shared__ float Bs[32 * BP];   // [k][n swizzled]

    const int tid = threadIdx.x;
    const int tx = tid & 15;
    const int ty = tid >> 4;
    const int m0 = blockIdx.x * 128;
    const int t3 = blockIdx.y;      // 0=q, 1=k, 2=v
    const int sx = (tx & 8) >> 2;

    ull pacc[8][4];
#pragma unroll
    for (int i = 0; i < 8; i++)
#pragma unroll
        for (int j = 0; j < 4; j++) pacc[i][j] = 0ull;

    const float4* A4 = reinterpret_cast<const float4*>(A);
    const float4* B4 = reinterpret_cast<const float4*>(B);

    for (int kc = 0; kc < 128; kc += 32) {
#pragma unroll
        for (int t = 0; t < 4; t++) {
            int flat = tid + t * 256;
            int m = flat >> 3;
            int k4 = flat & 7;
            float4 v = A4[(size_t)(m0 + m) * 32 + (kc >> 2) + k4];
            As[(k4 * 4 + 0) * 132 + m] = v.x;
            As[(k4 * 4 + 1) * 132 + m] = v.y;
            As[(k4 * 4 + 2) * 132 + m] = v.z;
            As[(k4 * 4 + 3) * 132 + m] = v.w;
        }
#pragma unroll
        for (int t = 0; t < 4; t++) {
            int flat = tid + t * 256;
            int kk = flat >> 5;
            int n4 = flat & 31;
            float4 v = B4[(size_t)(kc + kk) * 96 + t3 * 32 + n4];
            int w = kk * BP + n4 * 4 + ((n4 & 8) >> 2) + ((n4 & 16) >> 2);
            *reinterpret_cast<float2*>(&Bs[w]) = make_float2(v.x, v.y);
            *reinterpret_cast<float2*>(&Bs[w + 2]) = make_float2(v.z, v.w);
        }
        __syncthreads();

#pragma unroll 8
        for (int kk = 0; kk < 32; kk++) {
            float av[8];
            *reinterpret_cast<float4*>(&av[0]) =
                *reinterpret_cast<const float4*>(&As[kk * 132 + ty * 4]);
            *reinterpret_cast<float4*>(&av[4]) =
                *reinterpret_cast<const float4*>(&As[kk * 132 + 64 + ty * 4]);
            const float* br = &Bs[kk * BP];
            ull bp0 = *reinterpret_cast<const ull*>(&br[tx * 4 + sx]);
            ull bp1 = *reinterpret_cast<const ull*>(&br[tx * 4 + 2 + sx]);
            ull bp2 = *reinterpret_cast<const ull*>(&br[68 + tx * 4 + sx]);
            ull bp3 = *reinterpret_cast<const ull*>(&br[68 + tx * 4 + 2 + sx]);
#pragma unroll
            for (int i = 0; i < 8; i++) {
                ull aa = pack_dup(av[i]);
                ffma2(pacc[i][0], aa, bp0);
                ffma2(pacc[i][1], aa, bp1);
                ffma2(pacc[i][2], aa, bp2);
                ffma2(pacc[i][3], aa, bp3);
            }
        }
        __syncthreads();
    }

    float* dst = (t3 == 0) ? g_q : ((t3 == 1) ? g_k : g_v);
    const float scale = (t3 == 0) ? 0.17677669529663687f : 1.0f;  // 32^-0.5

#pragma unroll
    for (int ih = 0; ih < 2; ih++) {
#pragma unroll
        for (int i = 0; i < 4; i++) {
            int r = ih * 64 + ty * 4 + i;
            int gm = m0 + r;
            int b = gm / 49;
            int n = gm - b * 49;
#pragma unroll
            for (int jh = 0; jh < 2; jh++) {
                int c = jh * 64 + tx * 4;
                int h = c >> 5;
                int d = c & 31;
                ull p0 = pacc[ih * 4 + i][jh * 2 + 0];
                ull p1 = pacc[ih * 4 + i][jh * 2 + 1];
                float4 o;
                o.x = (lo32(p0) + bias[t3 * 128 + c + 0]) * scale;
                o.y = (hi32(p0) + bias[t3 * 128 + c + 1]) * scale;
                o.z = (lo32(p1) + bias[t3 * 128 + c + 2]) * scale;
                o.w = (hi32(p1) + bias[t3 * 128 + c + 3]) * scale;
                *reinterpret_cast<float4*>(
                    &dst[(((size_t)b * H_HEADS + h) * N_TOK + n) * HD + d]) = o;
            }
        }
    }
}

// ---------------------------------------------------------------------------
// Attention v4: shuffle softmax + conflict-free K tile + paired-m FFMA2 PV.
// ---------------------------------------------------------------------------
__global__ __launch_bounds__(128) void attn_kernel() {
    __shared__ float qs[56 * 33];    // [n][k]
    __shared__ float ks_t[32 * 68];  // [k][m staggered: rows>=32 shifted +2]
    __shared__ float vs[49 * 36];    // [m][d]
    __shared__ float P[56 * 54];     // normalized probs [n][m], even pitch

    const int tid = threadIdx.x;
    const int b = blockIdx.x;
    const int h = blockIdx.y;

    const size_t base4 = (((size_t)b * H_HEADS + h) * N_TOK) * 8;  // float4 units
    const float4* q4 = reinterpret_cast<const float4*>(g_q);
    const float4* k4p = reinterpret_cast<const float4*>(g_k);
    const float4* v4 = reinterpret_cast<const float4*>(g_v);
    for (int f = tid; f < 49 * 8; f += 128) {
        int row = f >> 3;
        int c4 = f & 7;
        float4 vq = q4[base4 + f];
        float4 vk = k4p[base4 + f];
        float4 vv = v4[base4 + f];
        int o = row * 33 + c4 * 4;
        qs[o + 0] = vq.x; qs[o + 1] = vq.y; qs[o + 2] = vq.z; qs[o + 3] = vq.w;
        int rsw = row + ((row & 32) >> 4);  // rows >=32 shifted +2 (32,33 unused)
        ks_t[(c4 * 4 + 0) * 68 + rsw] = vk.x;
        ks_t[(c4 * 4 + 1) * 68 + rsw] = vk.y;
        ks_t[(c4 * 4 + 2) * 68 + rsw] = vk.z;
        ks_t[(c4 * 4 + 3) * 68 + rsw] = vk.w;
        *reinterpret_cast<float4*>(&vs[row * 36 + c4 * 4]) = vv;
    }
    __syncthreads();

    const int rowg = tid >> 4;   // 0..7
    const int colg = tid & 15;   // 0..15
    const int sw = (colg & 8) >> 2;

    // --- S = q k^T (FFMA2 over col pairs, conflict-free K reads) ---
    ull pacc[7][2];
#pragma unroll
    for (int a = 0; a < 7; a++) { pacc[a][0] = 0ull; pacc[a][1] = 0ull; }

#pragma unroll 4
    for (int k = 0; k < 32; k++) {
        ull kp0 = *reinterpret_cast<const ull*>(&ks_t[k * 68 + colg * 4 + sw]);
        ull kp1 = *reinterpret_cast<const ull*>(&ks_t[k * 68 + colg * 4 + 2 + sw]);
#pragma unroll
        for (int a = 0; a < 7; a++) {
            ull qq = pack_dup(qs[(rowg * 7 + a) * 33 + k]);
            ffma2(pacc[a][0], qq, kp0);
            ffma2(pacc[a][1], qq, kp1);
        }
    }

    // --- fused bias add + softmax via half-warp shuffles, write P ---
    {
        const float* cb = g_comb + ((size_t)((b & 63) * H_HEADS + h)) * 2401;
#pragma unroll
        for (int a = 0; a < 7; a++) {
            int n = rowg * 7 + a;
            float v0 = lo32(pacc[a][0]);
            float v1 = hi32(pacc[a][0]);
            float v2 = lo32(pacc[a][1]);
            float v3 = hi32(pacc[a][1]);
            int m0c = colg * 4;
            if (n < 49) {
                const float* cr = cb + n * 49 + m0c;
                v0 = (m0c + 0 < 49) ? v0 + cr[0] : -1e30f;
                v1 = (m0c + 1 < 49) ? v1 + cr[1] : -1e30f;
                v2 = (m0c + 2 < 49) ? v2 + cr[2] : -1e30f;
                v3 = (m0c + 3 < 49) ? v3 + cr[3] : -1e30f;
            } else {
                v0 = v1 = v2 = v3 = -1e30f;
            }
            float mx = fmaxf(fmaxf(v0, v1), fmaxf(v2, v3));
#pragma unroll
            for (int ofs = 1; ofs < 16; ofs <<= 1)
                mx = fmaxf(mx, __shfl_xor_sync(0xffffffffu, mx, ofs, 16));
            float e0 = __expf(v0 - mx);
            float e1 = __expf(v1 - mx);
            float e2 = __expf(v2 - mx);
            float e3 = __expf(v3 - mx);
            float sm = (e0 + e1) + (e2 + e3);
#pragma unroll
            for (int ofs = 1; ofs < 16; ofs <<= 1)
                sm += __shfl_xor_sync(0xffffffffu, sm, ofs, 16);
            float inv = 1.0f / sm;
            float* pr = &P[n * 54 + m0c];
            if (m0c + 0 < 49) pr[0] = e0 * inv;
            if (m0c + 1 < 49) pr[1] = e1 * inv;
            if (m0c + 2 < 49) pr[2] = e2 * inv;
            if (m0c + 3 < 49) pr[3] = e3 * inv;
        }
    }
    __syncthreads();

    // --- O = P v : paired-m FFMA2, packed accumulators (same accum order) ---
    {
        ull acc2[7];
#pragma unroll
        for (int a = 0; a < 7; a++) acc2[a] = 0ull;

#pragma unroll 4
        for (int m = 0; m < 48; m += 2) {
            ull vf0 = *reinterpret_cast<const ull*>(&vs[m * 36 + colg * 2]);
            ull vf1 = *reinterpret_cast<const ull*>(&vs[(m + 1) * 36 + colg * 2]);
#pragma unroll
            for (int a = 0; a < 7; a++) {
                float2 pf = *reinterpret_cast<const float2*>(
                    &P[(rowg * 7 + a) * 54 + m]);
                ffma2(acc2[a], pack_dup(pf.x), vf0);
                ffma2(acc2[a], pack_dup(pf.y), vf1);
            }
        }
        {   // remainder m = 48
            ull vf0 = *reinterpret_cast<const ull*>(&vs[48 * 36 + colg * 2]);
#pragma unroll
            for (int a = 0; a < 7; a++)
                ffma2(acc2[a], pack_dup(P[(rowg * 7 + a) * 54 + 48]), vf0);
        }

#pragma unroll
        for (int a = 0; a < 7; a++) {
            int n = rowg * 7 + a;
            if (n < 49) {
                float2 o = make_float2(lo32(acc2[a]), hi32(acc2[a]));
                *reinterpret_cast<float2*>(
                    &g_ao[((size_t)b * N_TOK + n) * C_DIM + h * HD + colg * 2]) = o;
            }
        }
    }
}

// ---------------------------------------------------------------------------
// Proj GEMM (fp32, FFMA2, conflict-free B)
// ---------------------------------------------------------------------------
__global__ __launch_bounds__(256) void proj_gemm(const float* __restrict__ B,
                                                 const float* __restrict__ bias,
                                                 float* __restrict__ out) {
    __shared__ float As[32 * 132];
    __shared__ float Bs[32 * BP];

    const int tid = threadIdx.x;
    const int tx = tid & 15;
    const int ty = tid >> 4;
    const int m0 = blockIdx.x * 128;
    const int sx = (tx & 8) >> 2;

    ull pacc[8][4];
#pragma unroll
    for (int i = 0; i < 8; i++)
#pragma unroll
        for (int j = 0; j < 4; j++) pacc[i][j] = 0ull;

    const float4* A4 = reinterpret_cast<const float4*>(g_ao);
    const float4* B4 = reinterpret_cast<const float4*>(B);

    for (int kc = 0; kc < 128; kc += 32) {
#pragma unroll
        for (int t = 0; t < 4; t++) {
            int flat = tid + t * 256;
            int m = flat >> 3;
            int k4 = flat & 7;
            float4 v = A4[(size_t)(m0 + m) * 32 + (kc >> 2) + k4];
            As[(k4 * 4 + 0) * 132 + m] = v.x;
            As[(k4 * 4 + 1) * 132 + m] = v.y;
            As[(k4 * 4 + 2) * 132 + m] = v.z;
            As[(k4 * 4 + 3) * 132 + m] = v.w;
        }
#pragma unroll
        for (int t = 0; t < 4; t++) {
            int flat = tid + t * 256;
            int kk = flat >> 5;
            int n4 = flat & 31;
            float4 v = B4[(size_t)(kc + kk) * 32 + n4];
            int w = kk * BP + n4 * 4 + ((n4 & 8) >> 2) + ((n4 & 16) >> 2);
            *reinterpret_cast<float2*>(&Bs[w]) = make_float2(v.x, v.y);
            *reinterpret_cast<float2*>(&Bs[w + 2]) = make_float2(v.z, v.w);
        }
        __syncthreads();

#pragma unroll 8
        for (int kk = 0; kk < 32; kk++) {
            float av[8];
            *reinterpret_cast<float4*>(&av[0]) =
                *reinterpret_cast<const float4*>(&As[kk * 132 + ty * 4]);
            *reinterpret_cast<float4*>(&av[4]) =
                *reinterpret_cast<const float4*>(&As[kk * 132 + 64 + ty * 4]);
            const float* br = &Bs[kk * BP];
            ull bp0 = *reinterpret_cast<const ull*>(&br[tx * 4 + sx]);
            ull bp1 = *reinterpret_cast<const ull*>(&br[tx * 4 + 2 + sx]);
            ull bp2 = *reinterpret_cast<const ull*>(&br[68 + tx * 4 + sx]);
            ull bp3 = *reinterpret_cast<const ull*>(&br[68 + tx * 4 + 2 + sx]);
#pragma unroll
            for (int i = 0; i < 8; i++) {
                ull aa = pack_dup(av[i]);
                ffma2(pacc[i][0], aa, bp0);
                ffma2(pacc[i][1], aa, bp1);
                ffma2(pacc[i][2], aa, bp2);
                ffma2(pacc[i][3], aa, bp3);
            }
        }
        __syncthreads();
    }

#pragma unroll
    for (int ih = 0; ih < 2; ih++) {
#pragma unroll
        for (int i = 0; i < 4; i++) {
            int r = ih * 64 + ty * 4 + i;
            size_t gm = (size_t)m0 + r;
#pragma unroll
            for (int jh = 0; jh < 2; jh++) {
                int c = jh * 64 + tx * 4;
                ull p0 = pacc[ih * 4 + i][jh * 2 + 0];
                ull p1 = pacc[ih * 4 + i][jh * 2 + 1];
                float4 o;
                o.x = lo32(p0) + bias[c + 0];
                o.y = hi32(p0) + bias[c + 1];
                o.z = lo32(p1) + bias[c + 2];
                o.w = hi32(p1) + bias[c + 3];
                *reinterpret_cast<float4*>(&out[gm * C_DIM + c]) = o;
            }
        }
    }
}

// ---------------------------------------------------------------------------
extern "C" void kernel_launch(void* const* d_in, const int* in_sizes, int n_in,
                              void* d_out, int out_size) {
    const float* x          = (const float*)d_in[0];
    const float* mask       = (const float*)d_in[1];
    const float* qkv_w      = (const float*)d_in[2];
    const float* qkv_b      = (const float*)d_in[3];
    const float* proj_w     = (const float*)d_in[4];
    const float* proj_b     = (const float*)d_in[5];
    const float* bias_table = (const float*)d_in[6];
    const int*   rel32      = (const int*)d_in[7];

    int idx_stride = (in_sizes[7] >= 2401 * 2) ? 2 : 1;

    comb_kernel<<<dim3(64, H_HEADS), 256>>>(mask, bias_table, rel32, idx_stride);
    qkv_gemm<<<dim3(M_ROWS / 128, 3), 256>>>(x, qkv_w, qkv_b);
    attn_kernel<<<dim3(B_WIN, H_HEADS), 128>>>();
    proj_gemm<<<dim3(M_ROWS / 128, 1), 256>>>(proj_w, proj_b, (float*)d_out);
}